// round 5
// baseline (speedup 1.0000x reference)
#include <cuda_runtime.h>
#include <cstdint>

// CIN (xDeepFM) via mma.sync tf32 — round 5: 512 threads, 16 warps, 32x32 warp tiles.
// B=4096, F0=39, D=16, H=128/layer, Fi={39,128,128}.
// Z[h,n] = sum_{j,k} W[h, j*Fi+k] * (X0[j,n]*Xi[k,n]),  n=(b,d), 128 n per CTA.

#define THREADS 512
#define NBT     8
#define XROW    136     // smem row stride (floats) for X0/Xi

typedef unsigned long long u64;

// Pre-rounded (tf32) repacked weights
__device__ float W0pg[128 * 39 * 40];   // [h][j*40+kk], kk==39 -> 0
__device__ float W1pg[128 * 4992];
__device__ float W2pg[128 * 4992];

__device__ __forceinline__ uint32_t smem_u32(const void* p) {
    uint32_t a;
    asm("{ .reg .u64 t; cvta.to.shared.u64 t, %1; cvt.u32.u64 %0, t; }" : "=r"(a) : "l"(p));
    return a;
}
__device__ __forceinline__ float tf32r(float x) {
    uint32_t u; asm("cvt.rna.tf32.f32 %0, %1;" : "=r"(u) : "f"(x));
    return __uint_as_float(u);
}
__device__ __forceinline__ void cp16(uint32_t dst, const float* src) {
    asm volatile("cp.async.cg.shared.global [%0], [%1], 16;" :: "r"(dst), "l"(src) : "memory");
}
__device__ __forceinline__ void mma8(float c[4], const uint32_t a[4], uint32_t b0, uint32_t b1) {
    asm volatile(
        "mma.sync.aligned.m16n8k8.row.col.f32.tf32.tf32.f32 "
        "{%0,%1,%2,%3},{%4,%5,%6,%7},{%8,%9},{%0,%1,%2,%3};"
        : "+f"(c[0]), "+f"(c[1]), "+f"(c[2]), "+f"(c[3])
        : "r"(a[0]), "r"(a[1]), "r"(a[2]), "r"(a[3]), "r"(b0), "r"(b1));
}

// -------------------- weight prep ------------------------------------------
__global__ void pad_w0(const float* __restrict__ W0) {
    int i = blockIdx.x * 256 + threadIdx.x;
    if (i >= 128 * 1560) return;
    int h = i / 1560, r = i - h * 1560;
    int j = r / 40, kk = r - j * 40;
    W0pg[i] = (kk < 39) ? tf32r(W0[h * 1521 + j * 39 + kk]) : 0.f;
}
__global__ void round_w(const float* __restrict__ W, float* __restrict__ Wo) {
    int i = blockIdx.x * 256 + threadIdx.x;
    if (i < 128 * 4992) Wo[i] = tf32r(W[i]);
}

// -------------------- one layer GEMM ----------------------------------------
template <int CHUNK, int NCH, int WSTRIDE>
__device__ __forceinline__ void layer_mma(
    const float* __restrict__ Wg,   // [128][NCH*CHUNK]
    const float* xi,                // smem input rows
    const float* x0s,               // smem X0 rows (40, row 39 zero)
    float* wsm,                     // 3 stages of 128*WSTRIDE floats
    float acc[2][4][4],
    int tid)
{
    const int KROW   = NCH * CHUNK;
    const int KSTEPS = CHUNK / 8;
    const int SPR    = CHUNK / 4;   // 16B segs per row
    int lane = tid & 31, wid = tid >> 5;
    int grp = lane >> 2, tig = lane & 3;
    int h_base = (wid & 3) * 32, n_base = (wid >> 2) * 32;

    auto prefetch = [&](int c) {
        if (c < NCH) {
            float* dst = wsm + (c % 3) * (128 * WSTRIDE);
            const float* src = Wg + c * CHUNK;
            uint32_t du = smem_u32(dst);
            #pragma unroll
            for (int s = tid; s < 128 * SPR; s += THREADS) {
                int row = s / SPR, seg = s - row * SPR;
                cp16(du + (uint32_t)(row * WSTRIDE + seg * 4) * 4,
                     src + (size_t)row * KROW + seg * 4);
            }
        }
        asm volatile("cp.async.commit_group;" ::: "memory");
    };

    prefetch(0);
    prefetch(1);

    for (int c = 0; c < NCH; c++) {
        asm volatile("cp.async.wait_group 1;" ::: "memory");
        __syncthreads();                    // chunk c visible; stage (c+2)%3 free
        prefetch(c + 2);

        const float* ws = wsm + (c % 3) * (128 * WSTRIDE);
        int j   = (CHUNK == 40) ? c : (c >> 2);
        int kkb = (CHUNK == 40) ? 0 : ((c & 3) * 32);

        float x0v[4];
        #pragma unroll
        for (int nt = 0; nt < 4; nt++)
            x0v[nt] = x0s[j * XROW + n_base + nt * 8 + grp];

        #pragma unroll
        for (int ks = 0; ks < KSTEPS; ks++) {
            int k0 = ks * 8;
            uint32_t A[2][4];
            #pragma unroll
            for (int mt = 0; mt < 2; mt++) {
                const float* ab = ws + (h_base + mt * 16 + grp) * WSTRIDE + k0 + tig;
                A[mt][0] = __float_as_uint(ab[0]);
                A[mt][1] = __float_as_uint(ab[8 * WSTRIDE]);
                A[mt][2] = __float_as_uint(ab[4]);
                A[mt][3] = __float_as_uint(ab[8 * WSTRIDE + 4]);
            }
            int kk = kkb + k0 + tig;
            const float* xlo = xi + kk * XROW + n_base + grp;
            const float* xhi = xlo + 4 * XROW;
            #pragma unroll
            for (int nt = 0; nt < 4; nt++) {
                float p0 = x0v[nt] * xlo[nt * 8];
                float p1 = x0v[nt] * xhi[nt * 8];
                uint32_t B0, B1;
                asm("cvt.rna.tf32.f32 %0, %1;" : "=r"(B0) : "f"(p0));
                asm("cvt.rna.tf32.f32 %0, %1;" : "=r"(B1) : "f"(p1));
                #pragma unroll
                for (int mt = 0; mt < 2; mt++)
                    mma8(acc[mt][nt], A[mt], B0, B1);
            }
        }
    }
    asm volatile("cp.async.wait_group 0;" ::: "memory");
}

// -------------------- main fused kernel --------------------------------------
__global__ void __launch_bounds__(THREADS)
cin_mma(const float* __restrict__ x,
        const float* __restrict__ w0p, const float* __restrict__ w1p,
        const float* __restrict__ w2p,
        const float* __restrict__ b0, const float* __restrict__ b1,
        const float* __restrict__ b2,
        float* __restrict__ out)
{
    extern __shared__ float smf[];
    float* x0s = smf;                       // 40*136
    float* xis = smf + 40 * XROW;           // 128*136
    float* wsm = smf + (40 + 128) * XROW;   // 3 * 128*44

    int tid = threadIdx.x;
    int lane = tid & 31, wid = tid >> 5;
    int grp = lane >> 2, tig = lane & 3;
    int h_base = (wid & 3) * 32, n_base = (wid >> 2) * 32;
    int bbase = blockIdx.x * NBT;

    // stage X0: x[b, j, d] -> x0s[j][b*16+d]; zero pad row 39
    for (int i = tid; i < NBT * 624; i += THREADS) {
        int b = i / 624, r = i - b * 624;
        x0s[(r >> 4) * XROW + b * 16 + (r & 15)] = x[(size_t)(bbase + b) * 624 + r];
    }
    for (int i = tid; i < 128; i += THREADS) x0s[39 * XROW + i] = 0.f;
    __syncthreads();

    float acc[2][4][4];

    #pragma unroll 1
    for (int l = 0; l < 3; l++) {
        #pragma unroll
        for (int mt = 0; mt < 2; mt++)
            #pragma unroll
            for (int nt = 0; nt < 4; nt++)
                #pragma unroll
                for (int q = 0; q < 4; q++) acc[mt][nt][q] = 0.f;

        const float* bias;
        if (l == 0) {
            bias = b0;
            layer_mma<40, 39, 44>(w0p, x0s, x0s, wsm, acc, tid);
        } else if (l == 1) {
            bias = b1;
            layer_mma<32, 156, 36>(w1p, xis, x0s, wsm, acc, tid);
        } else {
            bias = b2;
            layer_mma<32, 156, 36>(w2p, xis, x0s, wsm, acc, tid);
        }

        __syncthreads();   // all reads of xis done before in-place overwrite

        // write Z (+bias) into xis
        #pragma unroll
        for (int mt = 0; mt < 2; mt++) {
            int h0 = h_base + mt * 16 + grp;
            float bv0 = __ldg(bias + h0), bv1 = __ldg(bias + h0 + 8);
            #pragma unroll
            for (int nt = 0; nt < 4; nt++) {
                int n = n_base + nt * 8 + 2 * tig;
                *(float2*)(xis + h0 * XROW + n) =
                    make_float2(acc[mt][nt][0] + bv0, acc[mt][nt][1] + bv0);
                *(float2*)(xis + (h0 + 8) * XROW + n) =
                    make_float2(acc[mt][nt][2] + bv1, acc[mt][nt][3] + bv1);
            }
        }
        __syncthreads();

        // d-sums -> out  (8 b x 128 h = 1024 rows)
        #pragma unroll
        for (int t = 0; t < 2; t++) {
            int idx = tid + THREADS * t;
            int b = idx >> 7, h = idx & 127;
            const float4* p4 = (const float4*)(xis + h * XROW + b * 16);
            float4 a = p4[0], c4 = p4[1], e = p4[2], g = p4[3];
            out[(size_t)(bbase + b) * 384 + l * 128 + h] =
                (a.x + a.y + a.z + a.w) + (c4.x + c4.y + c4.z + c4.w) +
                (e.x + e.y + e.z + e.w) + (g.x + g.y + g.z + g.w);
        }
        __syncthreads();
    }
}

// -------------------- launch -------------------------------------------------
extern "C" void kernel_launch(void* const* d_in, const int* in_sizes, int n_in,
                              void* d_out, int out_size) {
    const float* x  = (const float*)d_in[0];
    const float* W0 = (const float*)d_in[1];
    const float* b0 = (const float*)d_in[2];
    const float* W1 = (const float*)d_in[3];
    const float* b1 = (const float*)d_in[4];
    const float* W2 = (const float*)d_in[5];
    const float* b2 = (const float*)d_in[6];
    float* out = (float*)d_out;

    float *w0p, *w1p, *w2p;
    cudaGetSymbolAddress((void**)&w0p, W0pg);
    cudaGetSymbolAddress((void**)&w1p, W1pg);
    cudaGetSymbolAddress((void**)&w2p, W2pg);

    pad_w0<<<(128 * 1560 + 255) / 256, 256>>>(W0);
    round_w<<<(128 * 4992 + 255) / 256, 256>>>(W1, w1p);
    round_w<<<(128 * 4992 + 255) / 256, 256>>>(W2, w2p);

    // smem: x0s 40*136 + xis 128*136 + W stages 3*128*44  (floats)
    int smem_bytes = (40 * XROW + 128 * XROW + 3 * 128 * 44) * 4;
    cudaFuncSetAttribute(cin_mma, cudaFuncAttributeMaxDynamicSharedMemorySize, smem_bytes);
    cin_mma<<<4096 / NBT, THREADS, smem_bytes>>>(x, w0p, w1p, w2p, b0, b1, b2, out);
}

// round 6
// speedup vs baseline: 1.5385x; 1.5385x over previous
#include <cuda_runtime.h>
#include <cstdint>

// CIN (xDeepFM) via mma.sync tf32 — round 6.
// 16-batch CTA (N=256), 16 warps, warp tile 64h x 32n, fragment-ordered W.
// Z[h,n] = sum_{j,k} W[h, j*Fi+k] * (X0[j,n]*Xi[k,n]),  n=(b,d).

#define THREADS 512
#define NBT     16
#define XROW    264     // smem row stride (floats) for X0/Xi (conflict-free)

typedef unsigned long long u64;

// Fragment-ordered tf32 weights: [chunk][kstep][htile(8)][lane(32)][4]
__device__ float W0pg[39 * 5 * 8 * 32 * 4];    // layer0: CHUNK=40 (39 real + 1 pad)
__device__ float W1pg[156 * 4 * 8 * 32 * 4];   // layers 1/2: CHUNK=32
__device__ float W2pg[156 * 4 * 8 * 32 * 4];

__device__ __forceinline__ uint32_t smem_u32(const void* p) {
    uint32_t a;
    asm("{ .reg .u64 t; cvta.to.shared.u64 t, %1; cvt.u32.u64 %0, t; }" : "=r"(a) : "l"(p));
    return a;
}
__device__ __forceinline__ float tf32r(float x) {
    uint32_t u; asm("cvt.rna.tf32.f32 %0, %1;" : "=r"(u) : "f"(x));
    return __uint_as_float(u);
}
__device__ __forceinline__ void cp16(uint32_t dst, const float* src) {
    asm volatile("cp.async.cg.shared.global [%0], [%1], 16;" :: "r"(dst), "l"(src) : "memory");
}
__device__ __forceinline__ void mma8(float c[4], const uint32_t a[4], uint32_t b0, uint32_t b1) {
    asm volatile(
        "mma.sync.aligned.m16n8k8.row.col.f32.tf32.tf32.f32 "
        "{%0,%1,%2,%3},{%4,%5,%6,%7},{%8,%9},{%0,%1,%2,%3};"
        : "+f"(c[0]), "+f"(c[1]), "+f"(c[2]), "+f"(c[3])
        : "r"(a[0]), "r"(a[1]), "r"(a[2]), "r"(a[3]), "r"(b0), "r"(b1));
}

// -------------------- weight prep: fragment-order repack ---------------------
// layers 1/2: W[128][4992] -> frags, CHUNK=32, KSTEPS=4, NCH=156
__global__ void frag_w(const float* __restrict__ W, float* __restrict__ Wo) {
    int g = blockIdx.x * 256 + threadIdx.x;
    if (g >= 156 * 1024) return;
    int lane = g & 31, ht = (g >> 5) & 7, ks = (g >> 8) & 3, c = g >> 10;
    int grp = lane >> 2, tig = lane & 3;
    int row = ht * 16 + grp;
    int col = c * 32 + ks * 8 + tig;
    float4 v;
    v.x = tf32r(W[(size_t)row * 4992 + col]);
    v.y = tf32r(W[(size_t)(row + 8) * 4992 + col]);
    v.z = tf32r(W[(size_t)row * 4992 + col + 4]);
    v.w = tf32r(W[(size_t)(row + 8) * 4992 + col + 4]);
    ((float4*)Wo)[g] = v;
}
// layer0: W[128][1521] -> frags, CHUNK=40, KSTEPS=5, NCH=39 (k==39 is pad)
__global__ void frag_w0(const float* __restrict__ W) {
    int g = blockIdx.x * 256 + threadIdx.x;
    if (g >= 39 * 1280) return;
    int lane = g & 31, ht = (g >> 5) & 7;
    int r = g >> 8;              // ks + 5*c
    int ks = r % 5, c = r / 5;
    int grp = lane >> 2, tig = lane & 3;
    int row = ht * 16 + grp;
    int kl = ks * 8 + tig;       // <= 35
    int col = c * 39 + kl;
    float4 v;
    v.x = tf32r(W[(size_t)row * 1521 + col]);
    v.y = tf32r(W[(size_t)(row + 8) * 1521 + col]);
    v.z = (kl + 4 < 39) ? tf32r(W[(size_t)row * 1521 + col + 4]) : 0.f;
    v.w = (kl + 4 < 39) ? tf32r(W[(size_t)(row + 8) * 1521 + col + 4]) : 0.f;
    ((float4*)W0pg)[g] = v;
}

// -------------------- one layer GEMM ----------------------------------------
// Wg: fragment-ordered [NCH][KSTEPS][8][32][4]; wsm: 2 stages of 128*CHUNK floats.
template <int CHUNK, int KSTEPS, int NCH>
__device__ __forceinline__ void layer_mma(
    const float* __restrict__ Wg,
    const float* xi, const float* x0s,
    float* wsm, float acc[4][4][4], int tid)
{
    const int STAGE = 128 * CHUNK;           // floats per stage
    int lane = tid & 31, wid = tid >> 5;
    int grp = lane >> 2, tig = lane & 3;
    int ht_base = (wid & 1) * 4;             // h_base = ht_base*16
    int n_base = (wid >> 1) * 32;

    auto prefetch = [&](int c) {
        if (c < NCH) {
            uint32_t du = smem_u32(wsm + (c & 1) * STAGE);
            const float* src = Wg + (size_t)c * STAGE;
            #pragma unroll
            for (int s = tid; s < STAGE / 4; s += THREADS)
                cp16(du + (uint32_t)s * 16, src + s * 4);
        }
        asm volatile("cp.async.commit_group;" ::: "memory");
    };

    prefetch(0);
    prefetch(1);

    for (int c = 0; c < NCH; c++) {
        asm volatile("cp.async.wait_group 1;" ::: "memory");
        __syncthreads();                      // chunk c visible to all warps

        const float4* wf = (const float4*)(wsm + (c & 1) * STAGE);
        int j   = (CHUNK == 40) ? c : (c >> 2);
        int kkb = (CHUNK == 40) ? 0 : ((c & 3) * 32);

        float x0v[4];
        #pragma unroll
        for (int nt = 0; nt < 4; nt++)
            x0v[nt] = x0s[j * XROW + n_base + nt * 8 + grp];

        #pragma unroll
        for (int ks = 0; ks < KSTEPS; ks++) {
            uint32_t A[4][4];
            const float4* af = wf + ((ks * 8 + ht_base) * 32 + lane);
            #pragma unroll
            for (int mt = 0; mt < 4; mt++) {
                float4 av = af[mt * 32];
                A[mt][0] = __float_as_uint(av.x);
                A[mt][1] = __float_as_uint(av.y);
                A[mt][2] = __float_as_uint(av.z);
                A[mt][3] = __float_as_uint(av.w);
            }
            int kk = kkb + ks * 8 + tig;
            const float* xlo = xi + kk * XROW + n_base + grp;
            const float* xhi = xlo + 4 * XROW;
            #pragma unroll
            for (int nt = 0; nt < 4; nt++) {
                float p0 = x0v[nt] * xlo[nt * 8];
                float p1 = x0v[nt] * xhi[nt * 8];
                uint32_t B0, B1;
                asm("cvt.rna.tf32.f32 %0, %1;" : "=r"(B0) : "f"(p0));
                asm("cvt.rna.tf32.f32 %0, %1;" : "=r"(B1) : "f"(p1));
                #pragma unroll
                for (int mt = 0; mt < 4; mt++)
                    mma8(acc[mt][nt], A[mt], B0, B1);
            }
        }
        __syncthreads();                      // all warps done with stage c&1
        prefetch(c + 2);
    }
    asm volatile("cp.async.wait_group 0;" ::: "memory");
}

// -------------------- main fused kernel --------------------------------------
__global__ void __launch_bounds__(THREADS)
cin_mma(const float* __restrict__ x,
        const float* __restrict__ w0p, const float* __restrict__ w1p,
        const float* __restrict__ w2p,
        const float* __restrict__ b0, const float* __restrict__ b1,
        const float* __restrict__ b2,
        float* __restrict__ out)
{
    extern __shared__ float smf[];
    float* x0s = smf;                        // 40*264
    float* xis = smf + 40 * XROW;            // 128*264
    float* wsm = smf + (40 + 128) * XROW;    // 2 * 128*40

    int tid = threadIdx.x;
    int lane = tid & 31, wid = tid >> 5;
    int grp = lane >> 2, tig = lane & 3;
    int h_base = (wid & 1) * 64, n_base = (wid >> 1) * 32;
    int bbase = blockIdx.x * NBT;

    // stage X0: x[b, j, d] -> x0s[j][b*16+d]; zero pad row 39
    for (int i = tid; i < NBT * 624; i += THREADS) {
        int b = i / 624, r = i - b * 624;
        x0s[(r >> 4) * XROW + b * 16 + (r & 15)] = x[(size_t)(bbase + b) * 624 + r];
    }
    for (int i = tid; i < XROW; i += THREADS) x0s[39 * XROW + i] = 0.f;
    __syncthreads();

    float acc[4][4][4];

    #pragma unroll 1
    for (int l = 0; l < 3; l++) {
        #pragma unroll
        for (int mt = 0; mt < 4; mt++)
            #pragma unroll
            for (int nt = 0; nt < 4; nt++)
                #pragma unroll
                for (int q = 0; q < 4; q++) acc[mt][nt][q] = 0.f;

        const float* bias;
        if (l == 0) {
            bias = b0;
            layer_mma<40, 5, 39>(w0p, x0s, x0s, wsm, acc, tid);
        } else if (l == 1) {
            bias = b1;
            layer_mma<32, 4, 156>(w1p, xis, x0s, wsm, acc, tid);
        } else {
            bias = b2;
            layer_mma<32, 4, 156>(w2p, xis, x0s, wsm, acc, tid);
        }

        __syncthreads();   // all reads of xis done before in-place overwrite

        // write Z (+bias) into xis
        #pragma unroll
        for (int mt = 0; mt < 4; mt++) {
            int h0 = h_base + mt * 16 + grp;
            float bv0 = __ldg(bias + h0), bv1 = __ldg(bias + h0 + 8);
            #pragma unroll
            for (int nt = 0; nt < 4; nt++) {
                int n = n_base + nt * 8 + 2 * tig;
                *(float2*)(xis + h0 * XROW + n) =
                    make_float2(acc[mt][nt][0] + bv0, acc[mt][nt][1] + bv0);
                *(float2*)(xis + (h0 + 8) * XROW + n) =
                    make_float2(acc[mt][nt][2] + bv1, acc[mt][nt][3] + bv1);
            }
        }
        __syncthreads();

        // d-sums -> out  (16 b x 128 h = 2048 rows)
        #pragma unroll
        for (int t = 0; t < 4; t++) {
            int idx = tid + THREADS * t;
            int b = idx >> 7, h = idx & 127;
            const float4* p4 = (const float4*)(xis + h * XROW + b * 16);
            float4 a = p4[0], c4 = p4[1], e = p4[2], g = p4[3];
            out[(size_t)(bbase + b) * 384 + l * 128 + h] =
                (a.x + a.y + a.z + a.w) + (c4.x + c4.y + c4.z + c4.w) +
                (e.x + e.y + e.z + e.w) + (g.x + g.y + g.z + g.w);
        }
        __syncthreads();
    }
}

// -------------------- launch -------------------------------------------------
extern "C" void kernel_launch(void* const* d_in, const int* in_sizes, int n_in,
                              void* d_out, int out_size) {
    const float* x  = (const float*)d_in[0];
    const float* W0 = (const float*)d_in[1];
    const float* b0 = (const float*)d_in[2];
    const float* W1 = (const float*)d_in[3];
    const float* b1 = (const float*)d_in[4];
    const float* W2 = (const float*)d_in[5];
    const float* b2 = (const float*)d_in[6];
    float* out = (float*)d_out;

    float *w0p, *w1p, *w2p;
    cudaGetSymbolAddress((void**)&w0p, W0pg);
    cudaGetSymbolAddress((void**)&w1p, W1pg);
    cudaGetSymbolAddress((void**)&w2p, W2pg);

    frag_w0<<<(39 * 1280 + 255) / 256, 256>>>(W0);
    frag_w<<<(156 * 1024 + 255) / 256, 256>>>(W1, w1p);
    frag_w<<<(156 * 1024 + 255) / 256, 256>>>(W2, w2p);

    // smem: x0s 40*264 + xis 128*264 + W 2 stages of 128*40  (floats)
    int smem_bytes = ((40 + 128) * XROW + 2 * 128 * 40) * 4;
    cudaFuncSetAttribute(cin_mma, cudaFuncAttributeMaxDynamicSharedMemorySize, smem_bytes);
    cin_mma<<<4096 / NBT, THREADS, smem_bytes>>>(x, w0p, w1p, w2p, b0, b1, b2, out);
}